// round 11
// baseline (speedup 1.0000x reference)
#include <cuda_runtime.h>
#include <cuda_fp16.h>
#include <cstdint>

// StreamNet 3x3/s1 halo conv via HMMA (mma.sync m16n8k16 f16->f32), single fp16 pass.
// Round 11: warp = 1 row x 64 px x 32 co (full tile row). 128-thr CTA = 4 warps
// (tile 64px x 4 rows). Traffic 1.5 wf/MMA, ~100 regs -> 4 CTAs/SM.
// A smem: [r(6)][cipair(16)][Acol(72)] half2; data cols 2..67 (padded col t -> t+2).
// W smem: 18 regions (tap x kh) of 32 co rows x 32B, ci-half XOR-16B swizzle.

#define ACOL 72
#define PROW (ACOL * 4)             // 288 B per (r, cipair) row; 72 % 32 == 8 -> conflict-free
#define A_BYTES (6 * 16 * PROW)     // 27648
#define WOFF A_BYTES
#define WREG 1024                   // 32 co * 32 B
#define W_BYTES (18 * WREG)         // 18432
#define SMEM_TOTAL (A_BYTES + W_BYTES)   // 46080

__device__ __forceinline__ uint32_t smem_u32(const void* p) {
    uint32_t a;
    asm("{ .reg .u64 t; cvta.to.shared.u64 t, %1; cvt.u32.u64 %0, t; }" : "=r"(a) : "l"(p));
    return a;
}
__device__ __forceinline__ void ldmx4(uint32_t* r, uint32_t addr) {
    asm volatile("ldmatrix.sync.aligned.m8n8.x4.shared.b16 {%0,%1,%2,%3}, [%4];"
                 : "=r"(r[0]), "=r"(r[1]), "=r"(r[2]), "=r"(r[3]) : "r"(addr));
}
__device__ __forceinline__ void mma16816(float* d, const uint32_t* a,
                                         uint32_t b0, uint32_t b1) {
    asm volatile(
        "mma.sync.aligned.m16n8k16.row.col.f32.f16.f16.f32 "
        "{%0,%1,%2,%3}, {%4,%5,%6,%7}, {%8,%9}, {%0,%1,%2,%3};"
        : "+f"(d[0]), "+f"(d[1]), "+f"(d[2]), "+f"(d[3])
        : "r"(a[0]), "r"(a[1]), "r"(a[2]), "r"(a[3]), "r"(b0), "r"(b1));
}
__device__ __forceinline__ uint32_t h2b(__half2 h) {
    return *reinterpret_cast<uint32_t*>(&h);
}

__global__ __launch_bounds__(128, 4)
void streamnet_hmma_kernel(const float* __restrict__ x,
                           const float* __restrict__ rbuf,
                           const float* __restrict__ bbuf,
                           const float* __restrict__ W,
                           const float* __restrict__ bias,
                           float* __restrict__ out)
{
    extern __shared__ char smem[];
    const uint32_t sbase = smem_u32(smem);
    __half2* A2 = (__half2*)smem;

    const int tid  = threadIdx.x;
    const int lane = tid & 31;
    const int wid  = tid >> 5;
    const int x0   = blockIdx.x * 64;
    const int y    = blockIdx.y * 4;
    const int b    = blockIdx.z;

    // ---- stage W fp16: target-driven, shift-only indexing, ci-half XOR swizzle ----
    for (int i2 = tid; i2 < 4608; i2 += 128) {
        const int region = i2 >> 8;            // tap*2 + cihalf_sel
        const int co     = (i2 >> 3) & 31;
        const int j      = i2 & 7;
        const int tap    = region >> 1;
        const int ci     = ((region & 1) << 4) | (j << 1);
        const int src    = co * 288 + ci * 9 + tap;
        __half2 w2 = __floats2half2_rn(W[src], W[src + 9]);
        const int sw = (((j >> 2) ^ ((co >> 2) & 1)) << 4) | ((j & 3) << 2);
        *(uint32_t*)(smem + WOFF + region * WREG + co * 32 + sw) = h2b(w2);
    }

    // ---- stage input body: (r, p, k) -> padded cols x0+2+4k..+3, Acol 4+4k ----
    for (int t = tid; t < 1536; t += 128) {
        const int k = t & 15;
        const int p = (t >> 4) & 15;
        const int r = t >> 8;
        const int gi = y + r;                 // padded row
        const int bc = b * 32 + 2 * p;
        float4 a, c;
        if (gi >= 2) {
            const float* s = x + ((size_t)bc * 256 + (gi - 2)) * 256 + x0 + 4 * k;
            a = *(const float4*)s;
            c = *(const float4*)(s + 65536);
            if (x0 == 192 && k == 15) { a.w = 0.0f; c.w = 0.0f; }   // padded col 257
        } else {
            const float* s = bbuf + ((size_t)bc * 2 + gi) * 258 + x0 + 2 + 4 * k;
            float2 l0 = *(const float2*)s,         h0 = *(const float2*)(s + 2);
            float2 l1 = *(const float2*)(s + 516), h1 = *(const float2*)(s + 518);
            a = make_float4(l0.x, l0.y, h0.x, h0.y);
            c = make_float4(l1.x, l1.y, h1.x, h1.y);
        }
        uint4 st = make_uint4(h2b(__floats2half2_rn(a.x, c.x)),
                              h2b(__floats2half2_rn(a.y, c.y)),
                              h2b(__floats2half2_rn(a.z, c.z)),
                              h2b(__floats2half2_rn(a.w, c.w)));
        *(uint4*)&A2[(r * 16 + p) * ACOL + 4 + 4 * k] = st;
    }
    // ---- stage head cols (padded x0, x0+1 -> Acol 2,3) ----
    if (tid < 96) {
        const int p = tid & 15;
        const int r = tid >> 4;
        const int gi = y + r;
        const int bc = b * 32 + 2 * p;
        float2 a, c;
        if (gi < 2) {
            const float* s = bbuf + ((size_t)bc * 2 + gi) * 258 + x0;
            a = *(const float2*)s;
            c = *(const float2*)(s + 516);
        } else if (x0 == 0) {
            const float* s = rbuf + ((size_t)bc * 256 + (gi - 2)) * 2;
            a = *(const float2*)s;
            c = *(const float2*)(s + 512);
        } else {
            const float* s = x + ((size_t)bc * 256 + (gi - 2)) * 256 + x0 - 2;
            a = *(const float2*)s;
            c = *(const float2*)(s + 65536);
        }
        uint2 st = make_uint2(h2b(__floats2half2_rn(a.x, c.x)),
                              h2b(__floats2half2_rn(a.y, c.y)));
        *(uint2*)&A2[(r * 16 + p) * ACOL + 2] = st;
    }
    __syncthreads();

    // ---- mainloop: 4 warps = 4 rows; warp = 32 co x 64 px x 1 row ----
    const int rw = wid;                // output row 0..3

    float acc[2][8][4];                // [mt co-half][nt px-octet][4]
    #pragma unroll
    for (int mt = 0; mt < 2; mt++)
        #pragma unroll
        for (int nt = 0; nt < 8; nt++)
            #pragma unroll
            for (int j = 0; j < 4; j++) acc[mt][nt][j] = 0.0f;

    // ldmatrix lane addr: row = co (l&15), mat cihalf = l>>4, XOR-16B swizzle
    const uint32_t wbase = sbase + WOFF + (lane & 15) * 32 +
                           (((lane >> 4) ^ (((lane & 15) >> 2) & 1)) << 4);
    const char* abase = smem + (lane & 3) * PROW + ((lane >> 2) + 2) * 4;

    #pragma unroll
    for (int tap = 0; tap < 9; tap++) {
        const int dy = tap / 3, dx = tap - dy * 3;
        #pragma unroll
        for (int kh = 0; kh < 2; kh++) {
            uint32_t wf0[4], wf1[4];
            ldmx4(wf0, wbase + (tap * 2 + kh) * WREG);          // co 0-15
            ldmx4(wf1, wbase + (tap * 2 + kh) * WREG + 512);    // co 16-31
            const char* pb = abase + ((rw + dy) * 16 + kh * 8) * PROW + dx * 4;
            #pragma unroll
            for (int nt = 0; nt < 8; nt++) {
                uint32_t b0 = *(const uint32_t*)(pb + nt * 32);
                uint32_t b1 = *(const uint32_t*)(pb + nt * 32 + 4 * PROW);
                mma16816(acc[0][nt], wf0, b0, b1);
                mma16816(acc[1][nt], wf1, b0, b1);
            }
        }
    }

    // ---- epilogue: d0,d1 adjacent px -> float2; d2,d3 = co+8 plane ----
    const int oy = y + rw;
    #pragma unroll
    for (int mt = 0; mt < 2; mt++) {
        const int co = mt * 16 + (lane >> 2);
        const float bv0 = bias[co];
        const float bv1 = bias[co + 8];
        #pragma unroll
        for (int nt = 0; nt < 8; nt++) {
            const int px = x0 + nt * 8 + 2 * (lane & 3);
            float* p0 = &out[(((size_t)b * 32 + co) * 256 + oy) * 256 + px];
            float* p1 = p0 + 8 * 65536;
            *(float2*)p0 = make_float2(acc[mt][nt][0] + bv0, acc[mt][nt][1] + bv0);
            *(float2*)p1 = make_float2(acc[mt][nt][2] + bv1, acc[mt][nt][3] + bv1);
        }
    }
}

extern "C" void kernel_launch(void* const* d_in, const int* in_sizes, int n_in,
                              void* d_out, int out_size) {
    const float* x    = (const float*)d_in[0];
    const float* rbuf = (const float*)d_in[1];
    const float* bbuf = (const float*)d_in[2];
    const float* W    = (const float*)d_in[3];
    const float* bias = (const float*)d_in[4];
    float* out = (float*)d_out;

    cudaFuncSetAttribute(streamnet_hmma_kernel,
                         cudaFuncAttributeMaxDynamicSharedMemorySize, SMEM_TOTAL);

    dim3 grid(4, 64, 8);   // col-quarters x row-quads x batch = 2048 CTAs
    streamnet_hmma_kernel<<<grid, 128, SMEM_TOTAL>>>(x, rbuf, bbuf, W, bias, out);
}

// round 12
// speedup vs baseline: 1.3689x; 1.3689x over previous
#include <cuda_runtime.h>
#include <cuda_fp16.h>
#include <cstdint>

// StreamNet 3x3/s1 halo conv via HMMA (mma.sync m16n8k16 f16->f32), single fp16 pass.
// Round 12: R10 config (256 thr, warp = 1 row x 32 px x 32 co, 3 CTAs/SM) +
// W prepacked by a tiny pre-kernel into __device__ g_wpack (exact smem layout),
// so per-CTA W staging is a coalesced uint4 copy instead of 72B-strided LDG.
// A smem: [r(6)][cipair(16)][Acol(72)] half2; data cols 2..67 (padded col t -> t+2).
// W smem: 18 regions (tap x kh) of 32 co rows x 32B, ci-half XOR-16B swizzle.

#define ACOL 72
#define PROW (ACOL * 4)             // 288 B per (r, cipair) row; 72 % 32 == 8 -> conflict-free
#define A_BYTES (6 * 16 * PROW)     // 27648
#define WOFF A_BYTES
#define WREG 1024                   // 32 co * 32 B
#define W_BYTES (18 * WREG)         // 18432
#define SMEM_TOTAL (A_BYTES + W_BYTES)   // 46080

__device__ uint32_t g_wpack[4608];  // 18 regions x 32 co x 8 words (packed half2)

__device__ __forceinline__ uint32_t smem_u32(const void* p) {
    uint32_t a;
    asm("{ .reg .u64 t; cvta.to.shared.u64 t, %1; cvt.u32.u64 %0, t; }" : "=r"(a) : "l"(p));
    return a;
}
__device__ __forceinline__ void ldmx4(uint32_t* r, uint32_t addr) {
    asm volatile("ldmatrix.sync.aligned.m8n8.x4.shared.b16 {%0,%1,%2,%3}, [%4];"
                 : "=r"(r[0]), "=r"(r[1]), "=r"(r[2]), "=r"(r[3]) : "r"(addr));
}
__device__ __forceinline__ void mma16816(float* d, const uint32_t* a,
                                         uint32_t b0, uint32_t b1) {
    asm volatile(
        "mma.sync.aligned.m16n8k16.row.col.f32.f16.f16.f32 "
        "{%0,%1,%2,%3}, {%4,%5,%6,%7}, {%8,%9}, {%0,%1,%2,%3};"
        : "+f"(d[0]), "+f"(d[1]), "+f"(d[2]), "+f"(d[3])
        : "r"(a[0]), "r"(a[1]), "r"(a[2]), "r"(a[3]), "r"(b0), "r"(b1));
}
__device__ __forceinline__ uint32_t h2b(__half2 h) {
    return *reinterpret_cast<uint32_t*>(&h);
}

// ---- pre-kernel: pack W (fp32 OIHW) into the mainloop's smem word layout ----
// word index i = region*256 + co*8 + w, where w = ((j>>2)^((co>>2)&1))<<2 | (j&3),
// j = ci-pair within region, value = half2(W[co,ci,tap], W[co,ci+1,tap]).
__global__ void prep_w_kernel(const float* __restrict__ W) {
    const int i = blockIdx.x * 256 + threadIdx.x;
    if (i >= 4608) return;
    const int region = i >> 8;
    const int co     = (i >> 3) & 31;
    const int w      = i & 7;
    const int j      = (((w >> 2) ^ ((co >> 2) & 1)) << 2) | (w & 3);
    const int tap    = region >> 1;
    const int ci     = ((region & 1) << 4) | (j << 1);
    const int src    = co * 288 + ci * 9 + tap;
    g_wpack[i] = h2b(__floats2half2_rn(W[src], W[src + 9]));
}

__global__ __launch_bounds__(256, 3)
void streamnet_hmma_kernel(const float* __restrict__ x,
                           const float* __restrict__ rbuf,
                           const float* __restrict__ bbuf,
                           const float* __restrict__ bias,
                           float* __restrict__ out)
{
    extern __shared__ char smem[];
    const uint32_t sbase = smem_u32(smem);
    __half2* A2 = (__half2*)smem;

    const int tid  = threadIdx.x;
    const int lane = tid & 31;
    const int wid  = tid >> 5;
    const int x0   = blockIdx.x * 64;
    const int y    = blockIdx.y * 4;
    const int b    = blockIdx.z;

    // ---- stage W: linear coalesced copy of prepacked layout ----
    {
        const uint4* gw = (const uint4*)g_wpack;
        uint4* ws4 = (uint4*)(smem + WOFF);
        #pragma unroll
        for (int i = tid; i < 1152; i += 256) ws4[i] = gw[i];
    }

    // ---- stage input body: (r, p, k) -> padded cols x0+2+4k..+3, Acol 4+4k ----
    for (int t = tid; t < 1536; t += 256) {
        const int k = t & 15;
        const int p = (t >> 4) & 15;
        const int r = t >> 8;
        const int gi = y + r;                 // padded row
        const int bc = b * 32 + 2 * p;
        float4 a, c;
        if (gi >= 2) {
            const float* s = x + ((size_t)bc * 256 + (gi - 2)) * 256 + x0 + 4 * k;
            a = *(const float4*)s;
            c = *(const float4*)(s + 65536);
            if (x0 == 192 && k == 15) { a.w = 0.0f; c.w = 0.0f; }   // padded col 257
        } else {
            const float* s = bbuf + ((size_t)bc * 2 + gi) * 258 + x0 + 2 + 4 * k;
            float2 l0 = *(const float2*)s,         h0 = *(const float2*)(s + 2);
            float2 l1 = *(const float2*)(s + 516), h1 = *(const float2*)(s + 518);
            a = make_float4(l0.x, l0.y, h0.x, h0.y);
            c = make_float4(l1.x, l1.y, h1.x, h1.y);
        }
        uint4 st = make_uint4(h2b(__floats2half2_rn(a.x, c.x)),
                              h2b(__floats2half2_rn(a.y, c.y)),
                              h2b(__floats2half2_rn(a.z, c.z)),
                              h2b(__floats2half2_rn(a.w, c.w)));
        *(uint4*)&A2[(r * 16 + p) * ACOL + 4 + 4 * k] = st;
    }
    // ---- stage head cols (padded x0, x0+1 -> Acol 2,3) ----
    if (tid < 96) {
        const int p = tid & 15;
        const int r = tid >> 4;
        const int gi = y + r;
        const int bc = b * 32 + 2 * p;
        float2 a, c;
        if (gi < 2) {
            const float* s = bbuf + ((size_t)bc * 2 + gi) * 258 + x0;
            a = *(const float2*)s;
            c = *(const float2*)(s + 516);
        } else if (x0 == 0) {
            const float* s = rbuf + ((size_t)bc * 256 + (gi - 2)) * 2;
            a = *(const float2*)s;
            c = *(const float2*)(s + 512);
        } else {
            const float* s = x + ((size_t)bc * 256 + (gi - 2)) * 256 + x0 - 2;
            a = *(const float2*)s;
            c = *(const float2*)(s + 65536);
        }
        uint2 st = make_uint2(h2b(__floats2half2_rn(a.x, c.x)),
                              h2b(__floats2half2_rn(a.y, c.y)));
        *(uint2*)&A2[(r * 16 + p) * ACOL + 2] = st;
    }
    __syncthreads();

    // ---- mainloop: 8 warps = 4 rows x 2 px-halves; warp = 32co x 32px x 1 row ----
    const int rw = wid >> 1;           // output row 0..3
    const int cb = (wid & 1) * 32;     // px base

    float acc[2][4][4];                // [mt][nt][4]
    #pragma unroll
    for (int mt = 0; mt < 2; mt++)
        #pragma unroll
        for (int nt = 0; nt < 4; nt++)
            #pragma unroll
            for (int j = 0; j < 4; j++) acc[mt][nt][j] = 0.0f;

    // ldmatrix lane addr: row = co (l&15), mat cihalf = l>>4, XOR-16B swizzle
    const uint32_t wbase = sbase + WOFF + (lane & 15) * 32 +
                           (((lane >> 4) ^ (((lane & 15) >> 2) & 1)) << 4);
    const char* abase = smem + (lane & 3) * PROW + (cb + (lane >> 2) + 2) * 4;

    #pragma unroll
    for (int tap = 0; tap < 9; tap++) {
        const int dy = tap / 3, dx = tap - dy * 3;
        #pragma unroll
        for (int kh = 0; kh < 2; kh++) {
            uint32_t wf0[4], wf1[4];
            ldmx4(wf0, wbase + (tap * 2 + kh) * WREG);          // co 0-15
            ldmx4(wf1, wbase + (tap * 2 + kh) * WREG + 512);    // co 16-31
            const char* pb = abase + ((rw + dy) * 16 + kh * 8) * PROW + dx * 4;
            #pragma unroll
            for (int nt = 0; nt < 4; nt++) {
                uint32_t b0 = *(const uint32_t*)(pb + nt * 32);
                uint32_t b1 = *(const uint32_t*)(pb + nt * 32 + 4 * PROW);
                mma16816(acc[0][nt], wf0, b0, b1);
                mma16816(acc[1][nt], wf1, b0, b1);
            }
        }
    }

    // ---- epilogue: d0,d1 adjacent px -> float2; d2,d3 = co+8 plane ----
    const int oy = y + rw;
    #pragma unroll
    for (int mt = 0; mt < 2; mt++) {
        const int co = mt * 16 + (lane >> 2);
        const float bv0 = bias[co];
        const float bv1 = bias[co + 8];
        #pragma unroll
        for (int nt = 0; nt < 4; nt++) {
            const int px = x0 + cb + nt * 8 + 2 * (lane & 3);
            float* p0 = &out[(((size_t)b * 32 + co) * 256 + oy) * 256 + px];
            float* p1 = p0 + 8 * 65536;
            *(float2*)p0 = make_float2(acc[mt][nt][0] + bv0, acc[mt][nt][1] + bv0);
            *(float2*)p1 = make_float2(acc[mt][nt][2] + bv1, acc[mt][nt][3] + bv1);
        }
    }
}

extern "C" void kernel_launch(void* const* d_in, const int* in_sizes, int n_in,
                              void* d_out, int out_size) {
    const float* x    = (const float*)d_in[0];
    const float* rbuf = (const float*)d_in[1];
    const float* bbuf = (const float*)d_in[2];
    const float* W    = (const float*)d_in[3];
    const float* bias = (const float*)d_in[4];
    float* out = (float*)d_out;

    cudaFuncSetAttribute(streamnet_hmma_kernel,
                         cudaFuncAttributeMaxDynamicSharedMemorySize, SMEM_TOTAL);

    prep_w_kernel<<<18, 256>>>(W);

    dim3 grid(4, 64, 8);   // col-quarters x row-quads x batch = 2048 CTAs
    streamnet_hmma_kernel<<<grid, 256, SMEM_TOTAL>>>(x, rbuf, bbuf, bias, out);
}